// round 5
// baseline (speedup 1.0000x reference)
#include <cuda_runtime.h>

// Problem-fixed maxima (sizes also derived at runtime from in_sizes)
#define NMAX 100000
#define EMAX 1600000
#define HID  128

// ---------------- scratch (device globals: no allocation allowed) ----------
__device__ __align__(256) float g_bufA[(size_t)NMAX * HID];   // 51.2 MB
__device__ __align__(256) float g_bufB[(size_t)NMAX * HID];   // 51.2 MB
__device__ __align__(16)  int   g_eidx0[EMAX];
__device__ __align__(16)  int   g_eidx1[EMAX];
__device__ __align__(16)  int   g_rs0[NMAX + 1];
__device__ __align__(16)  int   g_rs1[NMAX + 1];
__device__ int g_do0[NMAX], g_di0[NMAX], g_do1[NMAX], g_di1[NMAX];
__device__ int g_cur0[NMAX], g_cur1[NMAX];
__device__ float g_ns0[NMAX], g_nd0[NMAX], g_ns1[NMAX], g_nd1[NMAX];

// ---------------- setup kernels --------------------------------------------
__global__ void zero_aux(int n) {
    int i = blockIdx.x * blockDim.x + threadIdx.x;
    if (i < n) {
        g_do0[i] = 0; g_di0[i] = 0; g_do1[i] = 0; g_di1[i] = 0;
        g_cur0[i] = 0; g_cur1[i] = 0;
    }
}

__global__ void count_deg(const int* __restrict__ s0, const int* __restrict__ d0,
                          const int* __restrict__ s1, const int* __restrict__ d1, int e) {
    int i = blockIdx.x * blockDim.x + threadIdx.x;
    if (i < e) {
        atomicAdd(&g_do0[s0[i]], 1);
        atomicAdd(&g_di0[d0[i]], 1);
        atomicAdd(&g_do1[s1[i]], 1);
        atomicAdd(&g_di1[d1[i]], 1);
    }
}

__global__ void norms_k(int n) {
    int i = blockIdx.x * blockDim.x + threadIdx.x;
    if (i < n) {
        g_ns0[i] = rsqrtf(fmaxf((float)g_do0[i], 1.0f));
        g_nd0[i] = rsqrtf(fmaxf((float)g_di0[i], 1.0f));
        g_ns1[i] = rsqrtf(fmaxf((float)g_do1[i], 1.0f));
        g_nd1[i] = rsqrtf(fmaxf((float)g_di1[i], 1.0f));
    }
}

// Single-block exclusive scan of deg[0..n) -> rs[0..n]  (n up to ~1M fine)
__global__ void scan_k(const int* __restrict__ deg, int* __restrict__ rs, int n) {
    __shared__ int part[1024];
    int tid = threadIdx.x;
    int chunk = (n + 1023) >> 10;
    int beg = tid * chunk; if (beg > n) beg = n;
    int end = beg + chunk; if (end > n) end = n;
    int sum = 0;
    for (int i = beg; i < end; ++i) sum += deg[i];
    part[tid] = sum;
    __syncthreads();
    for (int off = 1; off < 1024; off <<= 1) {
        int v = (tid >= off) ? part[tid - off] : 0;
        __syncthreads();
        part[tid] += v;
        __syncthreads();
    }
    int run = (tid == 0) ? 0 : part[tid - 1];
    for (int i = beg; i < end; ++i) { rs[i] = run; run += deg[i]; }
    if (tid == 1023) rs[n] = part[1023];
}

// eidx[rs[dst]+slot] = src   (slot via per-dst atomic cursor)
__global__ void fill_csr(const int* __restrict__ src, const int* __restrict__ dst,
                         const int* __restrict__ rs, int* __restrict__ cur,
                         int* __restrict__ eidx, int e) {
    int i = blockIdx.x * blockDim.x + threadIdx.x;
    if (i < e) {
        int d = dst[i];
        int p = atomicAdd(&cur[d], 1);
        eidx[rs[d] + p] = src[i];
    }
}

// ---------------- GEMM: C[m][n] = (sum_k A[m][k]*W[k][n] + bias[n]) * rowscale[m]
// 128x128 tile, 256 threads, 8x8 register microtile, BK=16.
template <int K>
__global__ __launch_bounds__(256)
void gemm_rs(const float* __restrict__ A, const float* __restrict__ W,
             const float* __restrict__ bias, const float* __restrict__ rowscale,
             float* __restrict__ C, int M) {
    constexpr int BM = 128, BK = 16;
    __shared__ float As[BK][BM];
    __shared__ float Ws[BK][HID];

    const int tid = threadIdx.x;
    const int block_m = blockIdx.x * BM;
    const int tx = tid & 15;
    const int ty = tid >> 4;
    const int row0 = ty * 8;
    const int colA = tx * 4;
    const int colB = 64 + tx * 4;

    float acc[8][8];
#pragma unroll
    for (int i = 0; i < 8; ++i)
#pragma unroll
        for (int j = 0; j < 8; ++j) acc[i][j] = 0.0f;

    for (int kt = 0; kt < K; kt += BK) {
        // Load A tile (BM x BK), transposed into As[k][m]; coalesced LDG over rows.
#pragma unroll
        for (int h = 0; h < 2; ++h) {
            int s = tid + h * 256;           // 512 float4 slots
            int kq = s >> 7;                 // 0..3
            int m = s & 127;
            int gm = block_m + m;
            float4 v = make_float4(0.f, 0.f, 0.f, 0.f);
            if (gm < M)
                v = *reinterpret_cast<const float4*>(A + (long)gm * K + kt + kq * 4);
            As[kq * 4 + 0][m] = v.x;
            As[kq * 4 + 1][m] = v.y;
            As[kq * 4 + 2][m] = v.z;
            As[kq * 4 + 3][m] = v.w;
        }
        // Load W tile (BK x 128), direct.
#pragma unroll
        for (int h = 0; h < 2; ++h) {
            int s = tid + h * 256;
            int k = s >> 5;
            int nq = s & 31;
            *reinterpret_cast<float4*>(&Ws[k][nq * 4]) =
                *reinterpret_cast<const float4*>(W + (long)(kt + k) * HID + nq * 4);
        }
        __syncthreads();
#pragma unroll
        for (int k = 0; k < BK; ++k) {
            float4 a0 = *reinterpret_cast<const float4*>(&As[k][row0]);
            float4 a1 = *reinterpret_cast<const float4*>(&As[k][row0 + 4]);
            float4 w0 = *reinterpret_cast<const float4*>(&Ws[k][colA]);
            float4 w1 = *reinterpret_cast<const float4*>(&Ws[k][colB]);
            float ra[8] = {a0.x, a0.y, a0.z, a0.w, a1.x, a1.y, a1.z, a1.w};
            float rw[8] = {w0.x, w0.y, w0.z, w0.w, w1.x, w1.y, w1.z, w1.w};
#pragma unroll
            for (int i = 0; i < 8; ++i)
#pragma unroll
                for (int j = 0; j < 8; ++j)
                    acc[i][j] = fmaf(ra[i], rw[j], acc[i][j]);
        }
        __syncthreads();
    }

    float4 bv0 = make_float4(0.f, 0.f, 0.f, 0.f), bv1 = bv0;
    if (bias) {
        bv0 = *reinterpret_cast<const float4*>(bias + colA);
        bv1 = *reinterpret_cast<const float4*>(bias + colB);
    }
#pragma unroll
    for (int i = 0; i < 8; ++i) {
        int gm = block_m + row0 + i;
        if (gm >= M) break;
        float rs = rowscale ? rowscale[gm] : 1.0f;
        float4 o0, o1;
        o0.x = (acc[i][0] + bv0.x) * rs;
        o0.y = (acc[i][1] + bv0.y) * rs;
        o0.z = (acc[i][2] + bv0.z) * rs;
        o0.w = (acc[i][3] + bv0.w) * rs;
        o1.x = (acc[i][4] + bv1.x) * rs;
        o1.y = (acc[i][5] + bv1.y) * rs;
        o1.z = (acc[i][6] + bv1.z) * rs;
        o1.w = (acc[i][7] + bv1.w) * rs;
        *reinterpret_cast<float4*>(C + (long)gm * HID + colA) = o0;
        *reinterpret_cast<float4*>(C + (long)gm * HID + colB) = o1;
    }
}

// ---------------- CSR aggregation + fused epilogue -------------------------
// out[v] = relu( (sum_{e in-edges of v} B[src_e]) * nd[v] + bias )
// One warp per node; lane owns a float4 (128 floats / 32 lanes).
__global__ void agg_relu(const int* __restrict__ eidx, const int* __restrict__ rs,
                         const float* __restrict__ B, const float* __restrict__ nd,
                         const float* __restrict__ bias, float* __restrict__ out, int n) {
    int t = blockIdx.x * blockDim.x + threadIdx.x;
    int v = t >> 5;
    int lane = t & 31;
    if (v >= n) return;
    int beg = rs[v], end = rs[v + 1];
    float4 acc = make_float4(0.f, 0.f, 0.f, 0.f);
    for (int i = beg; i < end; ++i) {
        int s = eidx[i];  // broadcast within warp
        float4 x = *reinterpret_cast<const float4*>(B + (long)s * HID + lane * 4);
        acc.x += x.x; acc.y += x.y; acc.z += x.z; acc.w += x.w;
    }
    float d = nd[v];
    float4 bv = *reinterpret_cast<const float4*>(bias + lane * 4);
    float4 o;
    o.x = fmaxf(fmaf(acc.x, d, bv.x), 0.f);
    o.y = fmaxf(fmaf(acc.y, d, bv.y), 0.f);
    o.z = fmaxf(fmaf(acc.z, d, bv.z), 0.f);
    o.w = fmaxf(fmaf(acc.w, d, bv.w), 0.f);
    *reinterpret_cast<float4*>(out + (long)v * HID + lane * 4) = o;
}

// ---------------- launch ----------------------------------------------------
extern "C" void kernel_launch(void* const* d_in, const int* in_sizes, int n_in,
                              void* d_out, int out_size) {
    const float* x  = (const float*)d_in[0];
    const float* We = (const float*)d_in[1];
    const float* be = (const float*)d_in[2];
    const float* W1 = (const float*)d_in[3];
    const float* b1 = (const float*)d_in[4];
    const float* W2 = (const float*)d_in[5];
    const float* b2 = (const float*)d_in[6];
    const int* src0 = (const int*)d_in[7];
    const int* dst0 = (const int*)d_in[8];
    const int* src1 = (const int*)d_in[9];
    const int* dst1 = (const int*)d_in[10];

    const int IN_FEATS = 256;
    int n = in_sizes[0] / IN_FEATS;
    int e = in_sizes[7];

    float *pA, *pB, *pns0, *pnd0, *pns1, *pnd1;
    int *prs0, *prs1, *pe0, *pe1, *pc0, *pc1, *pdi0, *pdi1;
    cudaGetSymbolAddress((void**)&pA,   g_bufA);
    cudaGetSymbolAddress((void**)&pB,   g_bufB);
    cudaGetSymbolAddress((void**)&pns0, g_ns0);
    cudaGetSymbolAddress((void**)&pnd0, g_nd0);
    cudaGetSymbolAddress((void**)&pns1, g_ns1);
    cudaGetSymbolAddress((void**)&pnd1, g_nd1);
    cudaGetSymbolAddress((void**)&prs0, g_rs0);
    cudaGetSymbolAddress((void**)&prs1, g_rs1);
    cudaGetSymbolAddress((void**)&pe0,  g_eidx0);
    cudaGetSymbolAddress((void**)&pe1,  g_eidx1);
    cudaGetSymbolAddress((void**)&pc0,  g_cur0);
    cudaGetSymbolAddress((void**)&pc1,  g_cur1);
    cudaGetSymbolAddress((void**)&pdi0, g_di0);
    cudaGetSymbolAddress((void**)&pdi1, g_di1);

    int nb = (n + 255) / 256;
    int eb = (e + 255) / 256;
    int gb = (n + 127) / 128;
    long agg_threads = (long)n * 32;
    int ab = (int)((agg_threads + 255) / 256);

    // --- graph prep: degrees, norms, CSR-by-dst for both layers ---
    zero_aux<<<nb, 256>>>(n);
    count_deg<<<eb, 256>>>(src0, dst0, src1, dst1, e);
    norms_k<<<nb, 256>>>(n);
    scan_k<<<1, 1024>>>(pdi0, prs0, n);
    scan_k<<<1, 1024>>>(pdi1, prs1, n);
    fill_csr<<<eb, 256>>>(src0, dst0, prs0, pc0, pe0, e);
    fill_csr<<<eb, 256>>>(src1, dst1, prs1, pc1, pe1, e);

    // --- embed: bufA = x @ We + be ---
    gemm_rs<256><<<gb, 256>>>(x, We, be, nullptr, pA, n);

    // --- layer 1: bufB = (bufA @ W1) * ns0 ; bufA = relu(agg * nd0 + b1) ---
    gemm_rs<128><<<gb, 256>>>(pA, W1, nullptr, pns0, pB, n);
    agg_relu<<<ab, 256>>>(pe0, prs0, pB, pnd0, b1, pA, n);

    // --- layer 2: bufB = (bufA @ W2) * ns1 ; out = relu(agg * nd1 + b2) ---
    gemm_rs<128><<<gb, 256>>>(pA, W2, nullptr, pns1, pB, n);
    agg_relu<<<ab, 256>>>(pe1, prs1, pB, pnd1, b2, (float*)d_out, n);
}

// round 6
// speedup vs baseline: 1.3226x; 1.3226x over previous
#include <cuda_runtime.h>

// Problem-fixed maxima (sizes also derived at runtime from in_sizes)
#define NMAX 100000
#define EMAX 1600000
#define HID  128

#define SCHUNK 1024
#define SBLOCKS_MAX 128   // ceil(NMAX/SCHUNK)=98 <= 128

// ---------------- scratch (device globals: no allocation allowed) ----------
__device__ __align__(256) float g_bufA[(size_t)NMAX * HID];   // 51.2 MB
__device__ __align__(256) float g_bufB[(size_t)NMAX * HID];   // 51.2 MB
__device__ __align__(16)  int   g_eidx0[EMAX];
__device__ __align__(16)  int   g_eidx1[EMAX];
__device__ __align__(16)  int   g_rs0[NMAX + 1];
__device__ __align__(16)  int   g_rs1[NMAX + 1];
__device__ int g_do0[NMAX], g_di0[NMAX], g_do1[NMAX], g_di1[NMAX];
__device__ int g_cur0[NMAX], g_cur1[NMAX];
__device__ float g_ns0[NMAX], g_nd0[NMAX], g_ns1[NMAX], g_nd1[NMAX];
__device__ int g_part[2][SBLOCKS_MAX];
__device__ int g_pscan[2][SBLOCKS_MAX];

// ---------------- setup kernels --------------------------------------------
__global__ void count_deg(const int* __restrict__ s0, const int* __restrict__ d0,
                          const int* __restrict__ s1, const int* __restrict__ d1, int e) {
    int i = blockIdx.x * blockDim.x + threadIdx.x;
    if (i < e) {
        atomicAdd(&g_do0[s0[i]], 1);
        atomicAdd(&g_di0[d0[i]], 1);
        atomicAdd(&g_do1[s1[i]], 1);
        atomicAdd(&g_di1[d1[i]], 1);
    }
}

__global__ void norms_k(int n) {
    int i = blockIdx.x * blockDim.x + threadIdx.x;
    if (i < n) {
        g_ns0[i] = rsqrtf(fmaxf((float)g_do0[i], 1.0f));
        g_nd0[i] = rsqrtf(fmaxf((float)g_di0[i], 1.0f));
        g_ns1[i] = rsqrtf(fmaxf((float)g_do1[i], 1.0f));
        g_nd1[i] = rsqrtf(fmaxf((float)g_di1[i], 1.0f));
    }
}

// ---------------- grid-wide exclusive scan (3 passes, 2 arrays batched) ----
// Pass 1: per-block (1024-elem chunk) totals.
__global__ void scan_pass1(const int* __restrict__ dA, const int* __restrict__ dB, int n) {
    const int* deg = blockIdx.y ? dB : dA;
    __shared__ int sh[256];
    int base = blockIdx.x * SCHUNK + threadIdx.x * 4;
    int s = 0;
#pragma unroll
    for (int q = 0; q < 4; ++q)
        if (base + q < n) s += deg[base + q];
    sh[threadIdx.x] = s;
    __syncthreads();
#pragma unroll
    for (int off = 128; off > 0; off >>= 1) {
        if (threadIdx.x < off) sh[threadIdx.x] += sh[threadIdx.x + off];
        __syncthreads();
    }
    if (threadIdx.x == 0) g_part[blockIdx.y][blockIdx.x] = sh[0];
}

// Pass 2: one block exclusive-scans both partial arrays (<=128 each);
// also writes rs[n] = grand total.
__global__ void scan_pass2(int* __restrict__ rsA, int* __restrict__ rsB,
                           int nblocks, int n) {
    __shared__ int sh[2][SBLOCKS_MAX];
    int a = threadIdx.x >> 7;
    int j = threadIdx.x & 127;
    int v = (j < nblocks) ? g_part[a][j] : 0;
    sh[a][j] = v;
    __syncthreads();
#pragma unroll
    for (int off = 1; off < SBLOCKS_MAX; off <<= 1) {
        int t = (j >= off) ? sh[a][j - off] : 0;
        __syncthreads();
        sh[a][j] += t;
        __syncthreads();
    }
    if (j < nblocks) g_pscan[a][j] = sh[a][j] - v;   // exclusive
    if (j == 127) {
        int total = sh[a][SBLOCKS_MAX - 1];
        (a ? rsB : rsA)[n] = total;
    }
}

// Pass 3: per-chunk exclusive scan + block offset -> rs[0..n)
__global__ void scan_pass3(const int* __restrict__ dA, const int* __restrict__ dB,
                           int* __restrict__ rsA, int* __restrict__ rsB, int n) {
    const int* deg = blockIdx.y ? dB : dA;
    int* rs = blockIdx.y ? rsB : rsA;
    __shared__ int sh[256];
    int base = blockIdx.x * SCHUNK + threadIdx.x * 4;
    int v[4];
    int s = 0;
#pragma unroll
    for (int q = 0; q < 4; ++q) {
        v[q] = (base + q < n) ? deg[base + q] : 0;
        s += v[q];
    }
    sh[threadIdx.x] = s;
    __syncthreads();
#pragma unroll
    for (int off = 1; off < 256; off <<= 1) {
        int t = (threadIdx.x >= off) ? sh[threadIdx.x - off] : 0;
        __syncthreads();
        sh[threadIdx.x] += t;
        __syncthreads();
    }
    int ex = sh[threadIdx.x] - s + g_pscan[blockIdx.y][blockIdx.x];
#pragma unroll
    for (int q = 0; q < 4; ++q) {
        if (base + q < n) { rs[base + q] = ex; ex += v[q]; }
    }
}

// eidx[rs[dst]+slot] = src   (slot via per-dst atomic cursor)
__global__ void fill_csr(const int* __restrict__ src, const int* __restrict__ dst,
                         const int* __restrict__ rs, int* __restrict__ cur,
                         int* __restrict__ eidx, int e) {
    int i = blockIdx.x * blockDim.x + threadIdx.x;
    if (i < e) {
        int d = dst[i];
        int p = atomicAdd(&cur[d], 1);
        eidx[rs[d] + p] = src[i];
    }
}

// ---------------- GEMM: C[m][n] = (sum_k A[m][k]*W[k][n] + bias[n]) * rowscale[m]
// 128x128 tile, 256 threads, 8x8 register microtile, BK=16.
template <int K>
__global__ __launch_bounds__(256)
void gemm_rs(const float* __restrict__ A, const float* __restrict__ W,
             const float* __restrict__ bias, const float* __restrict__ rowscale,
             float* __restrict__ C, int M) {
    constexpr int BM = 128, BK = 16;
    __shared__ float As[BK][BM];
    __shared__ float Ws[BK][HID];

    const int tid = threadIdx.x;
    const int block_m = blockIdx.x * BM;
    const int tx = tid & 15;
    const int ty = tid >> 4;
    const int row0 = ty * 8;
    const int colA = tx * 4;
    const int colB = 64 + tx * 4;

    float acc[8][8];
#pragma unroll
    for (int i = 0; i < 8; ++i)
#pragma unroll
        for (int j = 0; j < 8; ++j) acc[i][j] = 0.0f;

    for (int kt = 0; kt < K; kt += BK) {
        // Load A tile (BM x BK), transposed into As[k][m]; coalesced LDG over rows.
#pragma unroll
        for (int h = 0; h < 2; ++h) {
            int s = tid + h * 256;           // 512 float4 slots
            int kq = s >> 7;                 // 0..3
            int m = s & 127;
            int gm = block_m + m;
            float4 v = make_float4(0.f, 0.f, 0.f, 0.f);
            if (gm < M)
                v = *reinterpret_cast<const float4*>(A + (long)gm * K + kt + kq * 4);
            As[kq * 4 + 0][m] = v.x;
            As[kq * 4 + 1][m] = v.y;
            As[kq * 4 + 2][m] = v.z;
            As[kq * 4 + 3][m] = v.w;
        }
        // Load W tile (BK x 128), direct.
#pragma unroll
        for (int h = 0; h < 2; ++h) {
            int s = tid + h * 256;
            int k = s >> 5;
            int nq = s & 31;
            *reinterpret_cast<float4*>(&Ws[k][nq * 4]) =
                *reinterpret_cast<const float4*>(W + (long)(kt + k) * HID + nq * 4);
        }
        __syncthreads();
#pragma unroll
        for (int k = 0; k < BK; ++k) {
            float4 a0 = *reinterpret_cast<const float4*>(&As[k][row0]);
            float4 a1 = *reinterpret_cast<const float4*>(&As[k][row0 + 4]);
            float4 w0 = *reinterpret_cast<const float4*>(&Ws[k][colA]);
            float4 w1 = *reinterpret_cast<const float4*>(&Ws[k][colB]);
            float ra[8] = {a0.x, a0.y, a0.z, a0.w, a1.x, a1.y, a1.z, a1.w};
            float rw[8] = {w0.x, w0.y, w0.z, w0.w, w1.x, w1.y, w1.z, w1.w};
#pragma unroll
            for (int i = 0; i < 8; ++i)
#pragma unroll
                for (int j = 0; j < 8; ++j)
                    acc[i][j] = fmaf(ra[i], rw[j], acc[i][j]);
        }
        __syncthreads();
    }

    float4 bv0 = make_float4(0.f, 0.f, 0.f, 0.f), bv1 = bv0;
    if (bias) {
        bv0 = *reinterpret_cast<const float4*>(bias + colA);
        bv1 = *reinterpret_cast<const float4*>(bias + colB);
    }
#pragma unroll
    for (int i = 0; i < 8; ++i) {
        int gm = block_m + row0 + i;
        if (gm >= M) break;
        float rs = rowscale ? rowscale[gm] : 1.0f;
        float4 o0, o1;
        o0.x = (acc[i][0] + bv0.x) * rs;
        o0.y = (acc[i][1] + bv0.y) * rs;
        o0.z = (acc[i][2] + bv0.z) * rs;
        o0.w = (acc[i][3] + bv0.w) * rs;
        o1.x = (acc[i][4] + bv1.x) * rs;
        o1.y = (acc[i][5] + bv1.y) * rs;
        o1.z = (acc[i][6] + bv1.z) * rs;
        o1.w = (acc[i][7] + bv1.w) * rs;
        *reinterpret_cast<float4*>(C + (long)gm * HID + colA) = o0;
        *reinterpret_cast<float4*>(C + (long)gm * HID + colB) = o1;
    }
}

// ---------------- CSR aggregation + fused epilogue -------------------------
// out[v] = relu( (sum_{e in-edges of v} B[src_e]) * nd[v] + bias )
// One warp per node; lane owns a float4 (128 floats / 32 lanes).
// 2-way unrolled edge loop: two independent gather chains in flight.
__global__ void agg_relu(const int* __restrict__ eidx, const int* __restrict__ rs,
                         const float* __restrict__ B, const float* __restrict__ nd,
                         const float* __restrict__ bias, float* __restrict__ out, int n) {
    int t = blockIdx.x * blockDim.x + threadIdx.x;
    int v = t >> 5;
    int lane = t & 31;
    if (v >= n) return;
    int beg = rs[v], end = rs[v + 1];
    float4 acc0 = make_float4(0.f, 0.f, 0.f, 0.f);
    float4 acc1 = make_float4(0.f, 0.f, 0.f, 0.f);
    int i = beg;
    for (; i + 1 < end; i += 2) {
        int s0 = eidx[i];
        int s1 = eidx[i + 1];
        float4 x0 = *reinterpret_cast<const float4*>(B + (long)s0 * HID + lane * 4);
        float4 x1 = *reinterpret_cast<const float4*>(B + (long)s1 * HID + lane * 4);
        acc0.x += x0.x; acc0.y += x0.y; acc0.z += x0.z; acc0.w += x0.w;
        acc1.x += x1.x; acc1.y += x1.y; acc1.z += x1.z; acc1.w += x1.w;
    }
    if (i < end) {
        int s0 = eidx[i];
        float4 x0 = *reinterpret_cast<const float4*>(B + (long)s0 * HID + lane * 4);
        acc0.x += x0.x; acc0.y += x0.y; acc0.z += x0.z; acc0.w += x0.w;
    }
    acc0.x += acc1.x; acc0.y += acc1.y; acc0.z += acc1.z; acc0.w += acc1.w;
    float d = nd[v];
    float4 bv = *reinterpret_cast<const float4*>(bias + lane * 4);
    float4 o;
    o.x = fmaxf(fmaf(acc0.x, d, bv.x), 0.f);
    o.y = fmaxf(fmaf(acc0.y, d, bv.y), 0.f);
    o.z = fmaxf(fmaf(acc0.z, d, bv.z), 0.f);
    o.w = fmaxf(fmaf(acc0.w, d, bv.w), 0.f);
    *reinterpret_cast<float4*>(out + (long)v * HID + lane * 4) = o;
}

// ---------------- launch ----------------------------------------------------
extern "C" void kernel_launch(void* const* d_in, const int* in_sizes, int n_in,
                              void* d_out, int out_size) {
    const float* x  = (const float*)d_in[0];
    const float* We = (const float*)d_in[1];
    const float* be = (const float*)d_in[2];
    const float* W1 = (const float*)d_in[3];
    const float* b1 = (const float*)d_in[4];
    const float* W2 = (const float*)d_in[5];
    const float* b2 = (const float*)d_in[6];
    const int* src0 = (const int*)d_in[7];
    const int* dst0 = (const int*)d_in[8];
    const int* src1 = (const int*)d_in[9];
    const int* dst1 = (const int*)d_in[10];

    const int IN_FEATS = 256;
    int n = in_sizes[0] / IN_FEATS;
    int e = in_sizes[7];

    float *pA, *pB, *pns0, *pnd0, *pns1, *pnd1;
    int *prs0, *prs1, *pe0, *pe1, *pc0, *pc1;
    int *pdo0, *pdi0, *pdo1, *pdi1;
    cudaGetSymbolAddress((void**)&pA,   g_bufA);
    cudaGetSymbolAddress((void**)&pB,   g_bufB);
    cudaGetSymbolAddress((void**)&pns0, g_ns0);
    cudaGetSymbolAddress((void**)&pnd0, g_nd0);
    cudaGetSymbolAddress((void**)&pns1, g_ns1);
    cudaGetSymbolAddress((void**)&pnd1, g_nd1);
    cudaGetSymbolAddress((void**)&prs0, g_rs0);
    cudaGetSymbolAddress((void**)&prs1, g_rs1);
    cudaGetSymbolAddress((void**)&pe0,  g_eidx0);
    cudaGetSymbolAddress((void**)&pe1,  g_eidx1);
    cudaGetSymbolAddress((void**)&pc0,  g_cur0);
    cudaGetSymbolAddress((void**)&pc1,  g_cur1);
    cudaGetSymbolAddress((void**)&pdo0, g_do0);
    cudaGetSymbolAddress((void**)&pdi0, g_di0);
    cudaGetSymbolAddress((void**)&pdo1, g_do1);
    cudaGetSymbolAddress((void**)&pdi1, g_di1);

    int nb = (n + 255) / 256;
    int eb = (e + 255) / 256;
    int gb = (n + 127) / 128;
    long agg_threads = (long)n * 32;
    int ab = (int)((agg_threads + 255) / 256);
    int snb = (n + SCHUNK - 1) / SCHUNK;   // scan blocks (98 for N=100k)

    // --- zero degree/cursor arrays via memset nodes (graph-capturable) ---
    cudaMemsetAsync(pdo0, 0, (size_t)n * sizeof(int));
    cudaMemsetAsync(pdi0, 0, (size_t)n * sizeof(int));
    cudaMemsetAsync(pdo1, 0, (size_t)n * sizeof(int));
    cudaMemsetAsync(pdi1, 0, (size_t)n * sizeof(int));
    cudaMemsetAsync(pc0,  0, (size_t)n * sizeof(int));
    cudaMemsetAsync(pc1,  0, (size_t)n * sizeof(int));

    // --- graph prep: degrees, norms, CSR-by-dst for both layers ---
    count_deg<<<eb, 256>>>(src0, dst0, src1, dst1, e);
    norms_k<<<nb, 256>>>(n);
    {
        dim3 sg(snb, 2);
        scan_pass1<<<sg, 256>>>(pdi0, pdi1, n);
        scan_pass2<<<1, 256>>>(prs0, prs1, snb, n);
        scan_pass3<<<sg, 256>>>(pdi0, pdi1, prs0, prs1, n);
    }
    fill_csr<<<eb, 256>>>(src0, dst0, prs0, pc0, pe0, e);
    fill_csr<<<eb, 256>>>(src1, dst1, prs1, pc1, pe1, e);

    // --- embed: bufA = x @ We + be ---
    gemm_rs<256><<<gb, 256>>>(x, We, be, nullptr, pA, n);

    // --- layer 1: bufB = (bufA @ W1) * ns0 ; bufA = relu(agg * nd0 + b1) ---
    gemm_rs<128><<<gb, 256>>>(pA, W1, nullptr, pns0, pB, n);
    agg_relu<<<ab, 256>>>(pe0, prs0, pB, pnd0, b1, pA, n);

    // --- layer 2: bufB = (bufA @ W2) * ns1 ; out = relu(agg * nd1 + b2) ---
    gemm_rs<128><<<gb, 256>>>(pA, W2, nullptr, pns1, pB, n);
    agg_relu<<<ab, 256>>>(pe1, prs1, pB, pnd1, b2, (float*)d_out, n);
}

// round 8
// speedup vs baseline: 1.9783x; 1.4957x over previous
#include <cuda_runtime.h>
#include <cuda_bf16.h>
#include <cstdint>

// Problem-fixed maxima (sizes also derived at runtime from in_sizes)
#define NMAX 100000
#define EMAX 1600000
#define HID  128

#define SCHUNK 1024
#define SBLOCKS_MAX 128   // ceil(NMAX/SCHUNK)=98 <= 128

// ---------------- scratch (device globals: no allocation allowed) ----------
__device__ __align__(256) float g_bufA[(size_t)NMAX * HID];   // 51.2 MB
__device__ __align__(256) float g_bufB[(size_t)NMAX * HID];   // 51.2 MB
__device__ __align__(16)  int   g_eidx0[EMAX];
__device__ __align__(16)  int   g_eidx1[EMAX];
__device__ __align__(16)  int   g_rs0[NMAX + 1];
__device__ __align__(16)  int   g_rs1[NMAX + 1];
__device__ int g_do0[NMAX], g_di0[NMAX], g_do1[NMAX], g_di1[NMAX];
__device__ int g_cur0[NMAX], g_cur1[NMAX];
__device__ float g_ns0[NMAX], g_nd0[NMAX], g_ns1[NMAX], g_nd1[NMAX];
__device__ int g_part[2][SBLOCKS_MAX];
__device__ int g_pscan[2][SBLOCKS_MAX];
// W transposed + bf16 hi/lo split scratch: [HID rows][K<=256], K-contiguous
__device__ __align__(16) __nv_bfloat16 g_wHi[HID * 256];
__device__ __align__(16) __nv_bfloat16 g_wLo[HID * 256];

// ---------------- helpers ---------------------------------------------------
__device__ __forceinline__ uint32_t smem_u32(const void* p) {
    uint32_t a;
    asm("{ .reg .u64 t; cvta.to.shared.u64 t, %1; cvt.u32.u64 %0, t; }"
        : "=r"(a) : "l"(p));
    return a;
}

__device__ __forceinline__ uint32_t pack2(__nv_bfloat16 a, __nv_bfloat16 b) {
    return ((uint32_t)__bfloat16_as_ushort(b) << 16) | (uint32_t)__bfloat16_as_ushort(a);
}

#define LDSM4(r, addr) \
    asm volatile("ldmatrix.sync.aligned.m8n8.x4.shared.b16 {%0,%1,%2,%3}, [%4];" \
                 : "=r"((r)[0]), "=r"((r)[1]), "=r"((r)[2]), "=r"((r)[3]) \
                 : "r"(addr))

#define MMA16816(d, a, b0, b1) \
    asm volatile("mma.sync.aligned.m16n8k16.row.col.f32.bf16.bf16.f32 " \
                 "{%0,%1,%2,%3}, {%4,%5,%6,%7}, {%8,%9}, {%0,%1,%2,%3};" \
                 : "+f"((d)[0]), "+f"((d)[1]), "+f"((d)[2]), "+f"((d)[3]) \
                 : "r"((a)[0]), "r"((a)[1]), "r"((a)[2]), "r"((a)[3]), \
                   "r"(b0), "r"(b1))

// ---------------- setup kernels --------------------------------------------
__global__ void count_deg(const int* __restrict__ s0, const int* __restrict__ d0,
                          const int* __restrict__ s1, const int* __restrict__ d1, int e) {
    int i = blockIdx.x * blockDim.x + threadIdx.x;
    if (i < e) {
        atomicAdd(&g_do0[s0[i]], 1);
        atomicAdd(&g_di0[d0[i]], 1);
        atomicAdd(&g_do1[s1[i]], 1);
        atomicAdd(&g_di1[d1[i]], 1);
    }
}

__global__ void norms_k(int n) {
    int i = blockIdx.x * blockDim.x + threadIdx.x;
    if (i < n) {
        g_ns0[i] = rsqrtf(fmaxf((float)g_do0[i], 1.0f));
        g_nd0[i] = rsqrtf(fmaxf((float)g_di0[i], 1.0f));
        g_ns1[i] = rsqrtf(fmaxf((float)g_do1[i], 1.0f));
        g_nd1[i] = rsqrtf(fmaxf((float)g_di1[i], 1.0f));
    }
}

// W prep: transpose + bf16 hi/lo split.  W:[K][HID] -> wt{Hi,Lo}:[HID][K]
__global__ void w_prep(const float* __restrict__ W, int K) {
    int idx = blockIdx.x * blockDim.x + threadIdx.x;
    if (idx < K * HID) {
        int k = idx / HID, n = idx % HID;
        float w = W[idx];
        __nv_bfloat16 h = __float2bfloat16(w);
        float l = w - __bfloat162float(h);
        g_wHi[n * K + k] = h;
        g_wLo[n * K + k] = __float2bfloat16(l);
    }
}

// ---------------- grid-wide exclusive scan (3 passes, 2 arrays batched) ----
__global__ void scan_pass1(const int* __restrict__ dA, const int* __restrict__ dB, int n) {
    const int* deg = blockIdx.y ? dB : dA;
    __shared__ int sh[256];
    int base = blockIdx.x * SCHUNK + threadIdx.x * 4;
    int s = 0;
#pragma unroll
    for (int q = 0; q < 4; ++q)
        if (base + q < n) s += deg[base + q];
    sh[threadIdx.x] = s;
    __syncthreads();
#pragma unroll
    for (int off = 128; off > 0; off >>= 1) {
        if (threadIdx.x < off) sh[threadIdx.x] += sh[threadIdx.x + off];
        __syncthreads();
    }
    if (threadIdx.x == 0) g_part[blockIdx.y][blockIdx.x] = sh[0];
}

__global__ void scan_pass2(int* __restrict__ rsA, int* __restrict__ rsB,
                           int nblocks, int n) {
    __shared__ int sh[2][SBLOCKS_MAX];
    int a = threadIdx.x >> 7;
    int j = threadIdx.x & 127;
    int v = (j < nblocks) ? g_part[a][j] : 0;
    sh[a][j] = v;
    __syncthreads();
#pragma unroll
    for (int off = 1; off < SBLOCKS_MAX; off <<= 1) {
        int t = (j >= off) ? sh[a][j - off] : 0;
        __syncthreads();
        sh[a][j] += t;
        __syncthreads();
    }
    if (j < nblocks) g_pscan[a][j] = sh[a][j] - v;   // exclusive
    if (j == 127) {
        int total = sh[a][SBLOCKS_MAX - 1];
        (a ? rsB : rsA)[n] = total;
    }
}

__global__ void scan_pass3(const int* __restrict__ dA, const int* __restrict__ dB,
                           int* __restrict__ rsA, int* __restrict__ rsB, int n) {
    const int* deg = blockIdx.y ? dB : dA;
    int* rs = blockIdx.y ? rsB : rsA;
    __shared__ int sh[256];
    int base = blockIdx.x * SCHUNK + threadIdx.x * 4;
    int v[4];
    int s = 0;
#pragma unroll
    for (int q = 0; q < 4; ++q) {
        v[q] = (base + q < n) ? deg[base + q] : 0;
        s += v[q];
    }
    sh[threadIdx.x] = s;
    __syncthreads();
#pragma unroll
    for (int off = 1; off < 256; off <<= 1) {
        int t = (threadIdx.x >= off) ? sh[threadIdx.x - off] : 0;
        __syncthreads();
        sh[threadIdx.x] += t;
        __syncthreads();
    }
    int ex = sh[threadIdx.x] - s + g_pscan[blockIdx.y][blockIdx.x];
#pragma unroll
    for (int q = 0; q < 4; ++q) {
        if (base + q < n) { rs[base + q] = ex; ex += v[q]; }
    }
}

__global__ void fill_csr(const int* __restrict__ src, const int* __restrict__ dst,
                         const int* __restrict__ rs, int* __restrict__ cur,
                         int* __restrict__ eidx, int e) {
    int i = blockIdx.x * blockDim.x + threadIdx.x;
    if (i < e) {
        int d = dst[i];
        int p = atomicAdd(&cur[d], 1);
        eidx[rs[d] + p] = src[i];
    }
}

// ============== mma.sync bf16x3 GEMM (sm_100 legal, tensor pipe) ============
// C[m][n] = (sum_k A[m][k]*W[k][n] + bias[n]) * rowscale[m]
// A fp32 split on the fly; W pre-split in g_wHi/g_wLo [N][K] (K-contiguous).
// Block: 256 threads = 8 warps (4 m x 2 n), tile 128x128, K-chunk 64 in SMEM.
// SMEM rows padded to 144 B -> conflict-free ldmatrix.
#define ROWB 144                      // padded row stride in bytes (64 bf16 -> 72)
#define OFF_AHI 0
#define OFF_ALO (128 * ROWB)
#define OFF_WHI (2 * 128 * ROWB)
#define OFF_WLO (3 * 128 * ROWB)
#define GSMEM   (4 * 128 * ROWB)      // 73728 B

template <int K>
__global__ __launch_bounds__(256, 2)
void gemm_mma(const float* __restrict__ A,
              const __nv_bfloat16* __restrict__ whi,
              const __nv_bfloat16* __restrict__ wlo,
              const float* __restrict__ bias, const float* __restrict__ rowscale,
              float* __restrict__ C, int M) {
    extern __shared__ char sm[];
    const uint32_t smb = smem_u32(sm);
    const int tid = threadIdx.x;
    const int wid = tid >> 5;
    const int lane = tid & 31;
    const int warp_m = wid & 3;       // 0..3 -> 32 rows each
    const int warp_n = wid >> 2;      // 0..1 -> 64 cols each
    const int block_m = blockIdx.x * 128;

    float acc[2][8][4];
#pragma unroll
    for (int i = 0; i < 2; ++i)
#pragma unroll
        for (int j = 0; j < 8; ++j)
#pragma unroll
            for (int q = 0; q < 4; ++q) acc[i][j][q] = 0.0f;

    // per-lane ldmatrix address offsets
    const int q4 = lane >> 3, lr = lane & 7;
    const uint32_t laneA = (uint32_t)(((q4 & 1) * 8 + lr) * ROWB + (q4 >> 1) * 16);
    const uint32_t laneB = (uint32_t)(((q4 >> 1) * 8 + lr) * ROWB + (q4 & 1) * 16);
    const uint32_t aHiBase = smb + OFF_AHI + (uint32_t)(warp_m * 32) * ROWB + laneA;
    const uint32_t aLoBase = smb + OFF_ALO + (uint32_t)(warp_m * 32) * ROWB + laneA;
    const uint32_t wHiBase = smb + OFF_WHI + (uint32_t)(warp_n * 64) * ROWB + laneB;
    const uint32_t wLoBase = smb + OFF_WLO + (uint32_t)(warp_n * 64) * ROWB + laneB;

#pragma unroll 1
    for (int kc = 0; kc < K; kc += 64) {
        // ---- stage A chunk (128 x 64 fp32 -> bf16 hi/lo) ----
        {
            const int cq = (tid & 15) * 4;      // col within chunk (floats)
            const int r0 = tid >> 4;            // 0..15
#pragma unroll
            for (int it = 0; it < 8; ++it) {
                int r = r0 + it * 16;
                int gm = block_m + r;
                float4 v = make_float4(0.f, 0.f, 0.f, 0.f);
                if (gm < M)
                    v = *reinterpret_cast<const float4*>(A + (size_t)gm * K + kc + cq);
                __nv_bfloat16 h0 = __float2bfloat16(v.x);
                __nv_bfloat16 h1 = __float2bfloat16(v.y);
                __nv_bfloat16 h2 = __float2bfloat16(v.z);
                __nv_bfloat16 h3 = __float2bfloat16(v.w);
                uint2 hi = make_uint2(pack2(h0, h1), pack2(h2, h3));
                uint2 lo = make_uint2(
                    pack2(__float2bfloat16(v.x - __bfloat162float(h0)),
                          __float2bfloat16(v.y - __bfloat162float(h1))),
                    pack2(__float2bfloat16(v.z - __bfloat162float(h2)),
                          __float2bfloat16(v.w - __bfloat162float(h3))));
                uint32_t off = (uint32_t)(r * ROWB + cq * 2);
                *reinterpret_cast<uint2*>(sm + OFF_AHI + off) = hi;
                *reinterpret_cast<uint2*>(sm + OFF_ALO + off) = lo;
            }
        }
        // ---- stage W chunk (128 x 64 bf16 hi/lo) ----
        {
            const int cq = (tid & 7) * 8;       // col within chunk (bf16)
            const int r0 = tid >> 3;            // 0..31
#pragma unroll
            for (int it = 0; it < 4; ++it) {
                int r = r0 + it * 32;
                uint4 vh = *reinterpret_cast<const uint4*>(whi + (size_t)r * K + kc + cq);
                uint4 vl = *reinterpret_cast<const uint4*>(wlo + (size_t)r * K + kc + cq);
                uint32_t off = (uint32_t)(r * ROWB + cq * 2);
                *reinterpret_cast<uint4*>(sm + OFF_WHI + off) = vh;
                *reinterpret_cast<uint4*>(sm + OFF_WLO + off) = vl;
            }
        }
        __syncthreads();

        // ---- compute: 4 k16-steps ----
#pragma unroll
        for (int ks = 0; ks < 4; ++ks) {
            uint32_t ahi[2][4], alo[2][4];
#pragma unroll
            for (int ma = 0; ma < 2; ++ma) {
                uint32_t ao = (uint32_t)(ma * 16 * ROWB + ks * 32);
                LDSM4(ahi[ma], aHiBase + ao);
                LDSM4(alo[ma], aLoBase + ao);
            }
#pragma unroll
            for (int nb = 0; nb < 4; ++nb) {
                uint32_t bhi[4], blo[4];
                uint32_t bo = (uint32_t)(nb * 16 * ROWB + ks * 32);
                LDSM4(bhi, wHiBase + bo);
                LDSM4(blo, wLoBase + bo);
#pragma unroll
                for (int ma = 0; ma < 2; ++ma) {
                    MMA16816(acc[ma][nb * 2 + 0], ahi[ma], bhi[0], bhi[1]);
                    MMA16816(acc[ma][nb * 2 + 0], ahi[ma], blo[0], blo[1]);
                    MMA16816(acc[ma][nb * 2 + 0], alo[ma], bhi[0], bhi[1]);
                    MMA16816(acc[ma][nb * 2 + 1], ahi[ma], bhi[2], bhi[3]);
                    MMA16816(acc[ma][nb * 2 + 1], ahi[ma], blo[2], blo[3]);
                    MMA16816(acc[ma][nb * 2 + 1], alo[ma], bhi[2], bhi[3]);
                }
            }
        }
        __syncthreads();
    }

    // ---- epilogue ----
    const int g = lane >> 2, t = lane & 3;
#pragma unroll
    for (int ma = 0; ma < 2; ++ma) {
        int r0 = block_m + warp_m * 32 + ma * 16 + g;
        int r1 = r0 + 8;
        float rs0 = 1.0f, rs1 = 1.0f;
        if (rowscale) {
            if (r0 < M) rs0 = rowscale[r0];
            if (r1 < M) rs1 = rowscale[r1];
        }
#pragma unroll
        for (int na = 0; na < 8; ++na) {
            int col = warp_n * 64 + na * 8 + t * 2;
            float2 bv = make_float2(0.f, 0.f);
            if (bias) bv = *reinterpret_cast<const float2*>(bias + col);
            if (r0 < M) {
                float2 o;
                o.x = (acc[ma][na][0] + bv.x) * rs0;
                o.y = (acc[ma][na][1] + bv.y) * rs0;
                *reinterpret_cast<float2*>(C + (size_t)r0 * HID + col) = o;
            }
            if (r1 < M) {
                float2 o;
                o.x = (acc[ma][na][2] + bv.x) * rs1;
                o.y = (acc[ma][na][3] + bv.y) * rs1;
                *reinterpret_cast<float2*>(C + (size_t)r1 * HID + col) = o;
            }
        }
    }
}

// ---------------- CSR aggregation + fused epilogue -------------------------
__global__ void agg_relu(const int* __restrict__ eidx, const int* __restrict__ rs,
                         const float* __restrict__ B, const float* __restrict__ nd,
                         const float* __restrict__ bias, float* __restrict__ out, int n) {
    int t = blockIdx.x * blockDim.x + threadIdx.x;
    int v = t >> 5;
    int lane = t & 31;
    if (v >= n) return;
    int beg = rs[v], end = rs[v + 1];
    float4 acc0 = make_float4(0.f, 0.f, 0.f, 0.f);
    float4 acc1 = make_float4(0.f, 0.f, 0.f, 0.f);
    int i = beg;
    for (; i + 1 < end; i += 2) {
        int s0 = eidx[i];
        int s1 = eidx[i + 1];
        float4 x0 = *reinterpret_cast<const float4*>(B + (long)s0 * HID + lane * 4);
        float4 x1 = *reinterpret_cast<const float4*>(B + (long)s1 * HID + lane * 4);
        acc0.x += x0.x; acc0.y += x0.y; acc0.z += x0.z; acc0.w += x0.w;
        acc1.x += x1.x; acc1.y += x1.y; acc1.z += x1.z; acc1.w += x1.w;
    }
    if (i < end) {
        int s0 = eidx[i];
        float4 x0 = *reinterpret_cast<const float4*>(B + (long)s0 * HID + lane * 4);
        acc0.x += x0.x; acc0.y += x0.y; acc0.z += x0.z; acc0.w += x0.w;
    }
    acc0.x += acc1.x; acc0.y += acc1.y; acc0.z += acc1.z; acc0.w += acc1.w;
    float d = nd[v];
    float4 bv = *reinterpret_cast<const float4*>(bias + lane * 4);
    float4 o;
    o.x = fmaxf(fmaf(acc0.x, d, bv.x), 0.f);
    o.y = fmaxf(fmaf(acc0.y, d, bv.y), 0.f);
    o.z = fmaxf(fmaf(acc0.z, d, bv.z), 0.f);
    o.w = fmaxf(fmaf(acc0.w, d, bv.w), 0.f);
    *reinterpret_cast<float4*>(out + (long)v * HID + lane * 4) = o;
}

// ---------------- launch ----------------------------------------------------
extern "C" void kernel_launch(void* const* d_in, const int* in_sizes, int n_in,
                              void* d_out, int out_size) {
    const float* x  = (const float*)d_in[0];
    const float* We = (const float*)d_in[1];
    const float* be = (const float*)d_in[2];
    const float* W1 = (const float*)d_in[3];
    const float* b1 = (const float*)d_in[4];
    const float* W2 = (const float*)d_in[5];
    const float* b2 = (const float*)d_in[6];
    const int* src0 = (const int*)d_in[7];
    const int* dst0 = (const int*)d_in[8];
    const int* src1 = (const int*)d_in[9];
    const int* dst1 = (const int*)d_in[10];

    const int IN_FEATS = 256;
    int n = in_sizes[0] / IN_FEATS;
    int e = in_sizes[7];

    static bool attr_done = false;
    if (!attr_done) {
        cudaFuncSetAttribute(gemm_mma<256>, cudaFuncAttributeMaxDynamicSharedMemorySize, GSMEM);
        cudaFuncSetAttribute(gemm_mma<128>, cudaFuncAttributeMaxDynamicSharedMemorySize, GSMEM);
        attr_done = true;
    }

    float *pA, *pB, *pns0, *pnd0, *pns1, *pnd1;
    int *prs0, *prs1, *pe0, *pe1, *pc0, *pc1;
    int *pdo0, *pdi0, *pdo1, *pdi1;
    __nv_bfloat16 *pwHi, *pwLo;
    cudaGetSymbolAddress((void**)&pA,   g_bufA);
    cudaGetSymbolAddress((void**)&pB,   g_bufB);
    cudaGetSymbolAddress((void**)&pns0, g_ns0);
    cudaGetSymbolAddress((void**)&pnd0, g_nd0);
    cudaGetSymbolAddress((void**)&pns1, g_ns1);
    cudaGetSymbolAddress((void**)&pnd1, g_nd1);
    cudaGetSymbolAddress((void**)&prs0, g_rs0);
    cudaGetSymbolAddress((void**)&prs1, g_rs1);
    cudaGetSymbolAddress((void**)&pe0,  g_eidx0);
    cudaGetSymbolAddress((void**)&pe1,  g_eidx1);
    cudaGetSymbolAddress((void**)&pc0,  g_cur0);
    cudaGetSymbolAddress((void**)&pc1,  g_cur1);
    cudaGetSymbolAddress((void**)&pdo0, g_do0);
    cudaGetSymbolAddress((void**)&pdi0, g_di0);
    cudaGetSymbolAddress((void**)&pdo1, g_do1);
    cudaGetSymbolAddress((void**)&pdi1, g_di1);
    cudaGetSymbolAddress((void**)&pwHi, g_wHi);
    cudaGetSymbolAddress((void**)&pwLo, g_wLo);

    int nb = (n + 255) / 256;
    int eb = (e + 255) / 256;
    int gb = (n + 127) / 128;
    long agg_threads = (long)n * 32;
    int ab = (int)((agg_threads + 255) / 256);
    int snb = (n + SCHUNK - 1) / SCHUNK;

    // --- zero degree/cursor arrays via memset nodes (graph-capturable) ---
    cudaMemsetAsync(pdo0, 0, (size_t)n * sizeof(int));
    cudaMemsetAsync(pdi0, 0, (size_t)n * sizeof(int));
    cudaMemsetAsync(pdo1, 0, (size_t)n * sizeof(int));
    cudaMemsetAsync(pdi1, 0, (size_t)n * sizeof(int));
    cudaMemsetAsync(pc0,  0, (size_t)n * sizeof(int));
    cudaMemsetAsync(pc1,  0, (size_t)n * sizeof(int));

    // --- graph prep: degrees, norms, CSR-by-dst for both layers ---
    count_deg<<<eb, 256>>>(src0, dst0, src1, dst1, e);
    norms_k<<<nb, 256>>>(n);
    {
        dim3 sg(snb, 2);
        scan_pass1<<<sg, 256>>>(pdi0, pdi1, n);
        scan_pass2<<<1, 256>>>(prs0, prs1, snb, n);
        scan_pass3<<<sg, 256>>>(pdi0, pdi1, prs0, prs1, n);
    }
    fill_csr<<<eb, 256>>>(src0, dst0, prs0, pc0, pe0, e);
    fill_csr<<<eb, 256>>>(src1, dst1, prs1, pc1, pe1, e);

    // --- embed: bufA = x @ We + be ---
    w_prep<<<(256 * HID + 255) / 256, 256>>>(We, 256);
    gemm_mma<256><<<gb, 256, GSMEM>>>(x, pwHi, pwLo, be, nullptr, pA, n);

    // --- layer 1: bufB = (bufA @ W1) * ns0 ; bufA = relu(agg * nd0 + b1) ---
    w_prep<<<(128 * HID + 255) / 256, 256>>>(W1, 128);
    gemm_mma<128><<<gb, 256, GSMEM>>>(pA, pwHi, pwLo, nullptr, pns0, pB, n);
    agg_relu<<<ab, 256>>>(pe0, prs0, pB, pnd0, b1, pA, n);

    // --- layer 2: bufB = (bufA @ W2) * ns1 ; out = relu(agg * nd1 + b2) ---
    w_prep<<<(128 * HID + 255) / 256, 256>>>(W2, 128);
    gemm_mma<128><<<gb, 256, GSMEM>>>(pA, pwHi, pwLo, nullptr, pns1, pB, n);
    agg_relu<<<ab, 256>>>(pe1, prs1, pB, pnd1, b2, (float*)d_out, n);
}